// round 1
// baseline (speedup 1.0000x reference)
#include <cuda_runtime.h>
#include <cstdint>

// ---------------- problem constants ----------------
#define NATOMS   50000
#define S        7
#define NRBF     16
#define NPAIRS   28        // S*(S+1)/2
#define SUB      32        // NA*NZ
#define COLS     1008      // S*NRBF + NPAIRS*SUB
#define ANG_OFF  112       // S*NRBF
#define RC       0.51f
#define RMIN     0.08f
#define RCA      0.35f
#define RAMIN    0.08f
#define NA       8
#define NZ       4
#define ETA_R    1970.0f
#define ETA_A    1250.0f
#define ZETA     14.1f
#define PI_F     3.14159265358979323846f
#define PI_OVER_RC   (PI_F / RC)
#define PI_OVER_RCA  (PI_F / RCA)
#define DSTEP_R  0.026875f       // (RC-RMIN)/NRBF
#define DSTEP_A  0.03375f        // (RCA-RAMIN)/NA
#define ETA_A_LOG2E 1803.3688011112043f  // ETA_A * log2(e)

#define MAXP 1000000

// scratch (static device globals: allocation-free per harness rules)
__device__ float4        g_geo[MAXP];   // r_ij.xyz, d
__device__ unsigned short g_spec[MAXP]; // (si<<3) | sj
__device__ uint2         g_base[MAXP];  // radial scatter bases (in floats)

// ---------------- kernel 1: per-pair precompute ----------------
__global__ void prep_kernel(const int* __restrict__ atom_index,
                            const int* __restrict__ pairs,   // [2, P]
                            const float* __restrict__ d_ij,  // [P]
                            const float* __restrict__ r_ij,  // [P,3]
                            int P)
{
    int p = blockIdx.x * blockDim.x + threadIdx.x;
    if (p >= P) return;
    int i  = pairs[p];
    int j  = pairs[P + p];
    int si = atom_index[i];
    int sj = atom_index[j];
    float d = d_ij[p];
    float4 g;
    g.x = r_ij[3 * p + 0];
    g.y = r_ij[3 * p + 1];
    g.z = r_ij[3 * p + 2];
    g.w = d;
    g_geo[p]  = g;
    g_spec[p] = (unsigned short)((si << 3) | sj);
    g_base[p] = make_uint2((unsigned)(i * COLS + sj * NRBF),
                           (unsigned)(j * COLS + si * NRBF));
}

// ---------------- kernel 2: radial scatter (16 lanes per pair) ----------------
__global__ void radial_kernel(const float* __restrict__ d_ij,
                              float* __restrict__ out,
                              int P)
{
    int tid = blockIdx.x * blockDim.x + threadIdx.x;
    int p = tid >> 4;
    if (p >= P) return;
    int k = tid & 15;

    float d  = __ldg(d_ij + p);
    uint2 b  = g_base[p];

    float fc = (d < RC) ? (0.5f * __cosf(PI_OVER_RC * d) + 0.5f) : 0.0f;
    float dx = d - (RMIN + (float)k * DSTEP_R);
    float term = 0.25f * fc * __expf(-ETA_R * dx * dx);

    atomicAdd(out + b.x + k, term);   // 16 contiguous lanes -> coalesced RED
    atomicAdd(out + b.y + k, term);
}

// ---------------- kernel 3: angular (scalar phase + warp-wide phase) ----------------
__global__ __launch_bounds__(128)
void angular_kernel(const int* __restrict__ central,
                    const int* __restrict__ pidx,    // [2, T]
                    const int* __restrict__ sign12,  // [2, T]
                    float* __restrict__ out,
                    int T)
{
    __shared__ float4 shA[128];  // cos_a, sin_a, sum_d*0.5, fc0*fc1
    __shared__ int    shB[128];  // output base (floats)

    int tid = threadIdx.x;
    int t   = blockIdx.x * 128 + tid;

    if (t < T) {
        int p0  = pidx[t];
        int p1  = pidx[T + t];
        int sg0 = sign12[t];
        int sg1 = sign12[T + t];
        int c   = central[t];

        float4 g0 = g_geo[p0];
        float4 g1 = g_geo[p1];

        float dot = g0.x * g1.x + g0.y * g1.y + g0.z * g1.z;
        float ss  = (sg0 == sg1) ? 1.0f : -1.0f;
        float cosa = 0.95f * ss * dot / (g0.w * g1.w);
        float sina = sqrtf(fmaxf(0.0f, 1.0f - cosa * cosa));
        float sd   = 0.5f * (g0.w + g1.w);

        float fc0 = (g0.w < RCA) ? (0.5f * __cosf(PI_OVER_RCA * g0.w) + 0.5f) : 0.0f;
        float fc1 = (g1.w < RCA) ? (0.5f * __cosf(PI_OVER_RCA * g1.w) + 0.5f) : 0.0f;

        int sp0 = g_spec[p0];
        int sp1 = g_spec[p1];
        int s0 = (sg0 > 0) ? (sp0 & 7) : (sp0 >> 3);
        int s1 = (sg1 > 0) ? (sp1 & 7) : (sp1 >> 3);
        int a  = min(s0, s1);
        int b  = max(s0, s1);
        int tri = a * S - ((a * (a - 1)) >> 1) + (b - a);

        shA[tid] = make_float4(cosa, sina, sd, fc0 * fc1);
        shB[tid] = c * COLS + ANG_OFF + tri * SUB;
    }
    __syncthreads();

    int warp = tid >> 5;
    int lane = tid & 31;
    int az = lane >> 2;       // shfa index 0..7
    int zz = lane & 3;        // shfz index 0..3

    float shfa = RAMIN + (float)az * DSTEP_A;
    float angz = ((float)zz + 0.5f) * (PI_F / (float)NZ);
    float cz = cosf(angz);
    float sz = sinf(angz);

    int begin = warp * 32;
    int nv = T - (blockIdx.x * 128 + begin);
    if (nv > 32) nv = 32;

    for (int jj = 0; jj < nv; jj++) {
        float4 s = shA[begin + jj];     // broadcast LDS.128
        int base = shB[begin + jj];
        float dx = s.z - shfa;
        // u = (1 + cos(angle - shfz)) / 2, via angle-addition identity
        float u = fmaxf(0.0f, fmaf(0.5f * cz, s.x, fmaf(0.5f * sz, s.y, 0.5f)));
        // f1*f2 fused in log2 space: exp2(ZETA*log2(u) - ETA_A*log2e*dx^2)
        float e = fmaf(-ETA_A_LOG2E, dx * dx, ZETA * __log2f(u));
        float term = 2.0f * s.w * exp2f(e);
        atomicAdd(out + base + lane, term);  // 32 contiguous lanes -> 128B RED
    }
}

// ---------------- launch ----------------
extern "C" void kernel_launch(void* const* d_in, const int* in_sizes, int n_in,
                              void* d_out, int out_size)
{
    const int*   atom_index = (const int*)  d_in[0];
    const int*   pairs      = (const int*)  d_in[1];
    const float* d_ij       = (const float*)d_in[2];
    const float* r_ij       = (const float*)d_in[3];
    const int*   central    = (const int*)  d_in[4];
    const int*   pidx12     = (const int*)  d_in[5];
    const int*   sign12     = (const int*)  d_in[6];
    float* out = (float*)d_out;

    int P = in_sizes[2];      // d_ij element count
    int T = in_sizes[4];      // number of triples

    cudaMemsetAsync(d_out, 0, (size_t)out_size * sizeof(float));

    int threads = 256;
    prep_kernel<<<(P + threads - 1) / threads, threads>>>(atom_index, pairs, d_ij, r_ij, P);

    long long rad_threads = (long long)P * 16;
    radial_kernel<<<(int)((rad_threads + threads - 1) / threads), threads>>>(d_ij, out, P);

    angular_kernel<<<(T + 127) / 128, 128>>>(central, pidx12, sign12, out, T);
}